// round 3
// baseline (speedup 1.0000x reference)
#include <cuda_runtime.h>
#include <cstdint>
#include <cstddef>

// Problem constants
#define Bb 64
#define Tt 2048
#define Ii 128
#define Hh 256
#define Oo 128
#define Mm 256   // H - K1 + 1

// ---------------- scratch (device globals; no allocation allowed) ----------------
__device__ float g_uhats[Mm * Hh];
__device__ float g_vhats[Mm * Hh];
__device__ float g_bu[Mm];
__device__ float g_bv[Mm];
__device__ float g_U[Hh * Hh];
__device__ float g_V[Hh * Hh];
__device__ float g_W[Hh * Hh];
__device__ float g_xproj[(size_t)Bb * Tt * Hh];  // [B,T,H]
__device__ float g_hall [(size_t)Bb * Tt * Hh];  // [B,T,H]

// ---------------- helpers ----------------
__device__ __forceinline__ unsigned smem_u32(const void* p) {
    return (unsigned)__cvta_generic_to_shared(p);
}

// ============================================================================
// Kernel 1: build u_hats / v_hats (mask + flips) and betas = 2/<u,u>
// grid: 512 blocks (0..255 = u rows, 256..511 = v rows), 256 threads
// ============================================================================
__global__ __launch_bounds__(256) void prep_kernel(const float* __restrict__ u_raw,
                                                   const float* __restrict__ v_raw) {
    __shared__ float red[256];
    int i = blockIdx.x & 255;
    bool isv = blockIdx.x >= 256;
    int j = threadIdx.x;
    float val = 0.f;
    if (!isv) {
        // u_hats[i][j] = (j >= H-1-i) ? u_raw[i][H-1-j] : 0
        if (j >= 255 - i) val = u_raw[i * Hh + (255 - j)];
        g_uhats[i * Hh + j] = val;
    } else {
        // v_hats[i][j] = (j >= i) ? v_raw[M-1-i][H-1-j] : 0   (flip axes 0 and 1)
        if (j >= i) val = v_raw[(255 - i) * Hh + (255 - j)];
        g_vhats[i * Hh + j] = val;
    }
    red[j] = val * val;
    __syncthreads();
    for (int s = 128; s > 0; s >>= 1) {
        if (j < s) red[j] += red[j + s];
        __syncthreads();
    }
    if (j == 0) {
        float beta = 2.f / red[0];
        if (isv) g_bv[i] = beta; else g_bu[i] = beta;
    }
}

// ============================================================================
// Kernel 2: Householder chains. One warp per column of U (256) and V (256).
// Column kept in 8 regs/lane; 256 sequential rank-1 updates, column-parallel.
// grid: 64 blocks x 256 threads = 512 warps.
// ============================================================================
__global__ __launch_bounds__(256) void chain_kernel() {
    int warp = (blockIdx.x * blockDim.x + threadIdx.x) >> 5;
    int lane = threadIdx.x & 31;
    int col = warp & 255;
    bool isv = warp >= 256;
    const float* hats  = isv ? g_vhats : g_uhats;
    const float* betas = isv ? g_bv    : g_bu;
    float* out         = isv ? g_V     : g_U;

    float c[8];
#pragma unroll
    for (int q = 0; q < 8; q++) c[q] = ((lane + 32 * q) == col) ? 1.f : 0.f;

    for (int i = 0; i < Mm; i++) {
        float u[8];
#pragma unroll
        for (int q = 0; q < 8; q++) u[q] = hats[i * Hh + lane + 32 * q];
        float s = 0.f;
#pragma unroll
        for (int q = 0; q < 8; q++) s = fmaf(u[q], c[q], s);
#pragma unroll
        for (int off = 16; off > 0; off >>= 1)
            s += __shfl_xor_sync(0xffffffffu, s, off);
        float sc = betas[i] * s;
#pragma unroll
        for (int q = 0; q < 8; q++) c[q] = fmaf(-sc, u[q], c[q]);
    }
#pragma unroll
    for (int q = 0; q < 8; q++) out[(size_t)(lane + 32 * q) * Hh + col] = c[q];
}

// ============================================================================
// Kernel 3: W = (U * diag(sigmas)) @ V.  One block per row.
// ============================================================================
__global__ __launch_bounds__(256) void wgemm_kernel(const float* __restrict__ sig) {
    __shared__ float su[Hh];
    int r = blockIdx.x;
    int cidx = threadIdx.x;
    su[cidx] = g_U[r * Hh + cidx] * sig[cidx];
    __syncthreads();
    float acc = 0.f;
#pragma unroll 8
    for (int k = 0; k < Hh; k++) acc = fmaf(su[k], g_V[(size_t)k * Hh + cidx], acc);
    g_W[r * Hh + cidx] = acc;
}

// ============================================================================
// Kernel 4/6: generic SGEMM  C[MxN] = A[MxK] * B[NxK]^T + bias[N]
// 128x128 block tile, 8x8 per thread, BK=16, 256 threads.
// M,N,K assumed multiples of tile dims (true here).
// ============================================================================
__global__ __launch_bounds__(256) void sgemm_nt(const float* __restrict__ A,
                                                const float* __restrict__ Bm,
                                                const float* __restrict__ bias,
                                                float* __restrict__ C,
                                                int M, int N, int K) {
    __shared__ float As[16][128];
    __shared__ float Bs[16][128];
    int tid = threadIdx.x;
    int m0 = blockIdx.y * 128;
    int n0 = blockIdx.x * 128;
    int tx = tid & 15;   // n
    int ty = tid >> 4;   // m

    float acc[8][8];
#pragma unroll
    for (int i = 0; i < 8; i++)
#pragma unroll
        for (int j = 0; j < 8; j++) acc[i][j] = 0.f;

    for (int k0 = 0; k0 < K; k0 += 16) {
#pragma unroll
        for (int i = 0; i < 2; i++) {
            int fid = tid + i * 256;          // 0..511
            int row = fid >> 2;               // 0..127
            int c4  = fid & 3;                // 0..3
            float4 va = *(const float4*)(A  + (size_t)(m0 + row) * K + k0 + c4 * 4);
            As[c4 * 4 + 0][row] = va.x; As[c4 * 4 + 1][row] = va.y;
            As[c4 * 4 + 2][row] = va.z; As[c4 * 4 + 3][row] = va.w;
            float4 vb = *(const float4*)(Bm + (size_t)(n0 + row) * K + k0 + c4 * 4);
            Bs[c4 * 4 + 0][row] = vb.x; Bs[c4 * 4 + 1][row] = vb.y;
            Bs[c4 * 4 + 2][row] = vb.z; Bs[c4 * 4 + 3][row] = vb.w;
        }
        __syncthreads();
#pragma unroll
        for (int kk = 0; kk < 16; kk++) {
            float a[8], b[8];
            *(float4*)(a)     = *(const float4*)&As[kk][ty * 8];
            *(float4*)(a + 4) = *(const float4*)&As[kk][ty * 8 + 4];
            *(float4*)(b)     = *(const float4*)&Bs[kk][tx * 8];
            *(float4*)(b + 4) = *(const float4*)&Bs[kk][tx * 8 + 4];
#pragma unroll
            for (int i = 0; i < 8; i++)
#pragma unroll
                for (int j = 0; j < 8; j++)
                    acc[i][j] = fmaf(a[i], b[j], acc[i][j]);
        }
        __syncthreads();
    }

    float bv[8];
#pragma unroll
    for (int j = 0; j < 8; j++) bv[j] = bias[n0 + tx * 8 + j];
#pragma unroll
    for (int i = 0; i < 8; i++) {
        size_t base = (size_t)(m0 + ty * 8 + i) * N + n0 + tx * 8;
        float4 o0, o1;
        o0.x = acc[i][0] + bv[0]; o0.y = acc[i][1] + bv[1];
        o0.z = acc[i][2] + bv[2]; o0.w = acc[i][3] + bv[3];
        o1.x = acc[i][4] + bv[4]; o1.y = acc[i][5] + bv[5];
        o1.z = acc[i][6] + bv[6]; o1.w = acc[i][7] + bv[7];
        *(float4*)(C + base)     = o0;
        *(float4*)(C + base + 4) = o1;
    }
}

// ============================================================================
// Kernel 5: the recurrence. One 2-CTA cluster per batch element.
// CTA `half` owns h rows [half*128, half*128+128); W half lives in registers
// (128 regs/thread: threads 0..127 -> K-half 0, threads 128..255 -> K-half 1).
// h (256 floats) exchanged via DSMEM each step; barrier.cluster per step.
// h_t stored to g_hall; output projection deferred to a GEMM.
// ============================================================================
__global__ __launch_bounds__(256, 1) __cluster_dims__(2, 1, 1)
void rnn_kernel() {
    __shared__ float hbuf[2][256];
    __shared__ float part[128];

    unsigned rank;
    asm("mov.u32 %0, %%cluster_ctarank;" : "=r"(rank));
    int half = (int)rank;
    unsigned peer = rank ^ 1u;
    int b = blockIdx.x >> 1;
    int tid = threadIdx.x;
    bool low = tid < 128;
    int r = low ? tid : tid - 128;
    int kbase = low ? 0 : 128;
    int grow = half * 128 + r;   // global h row this thread contributes to

    // load W slice: W[grow][kbase + 0..127] into registers
    float w[128];
    const float4* wp = (const float4*)(g_W + (size_t)grow * Hh + kbase);
#pragma unroll
    for (int q = 0; q < 32; q++) {
        float4 v = wp[q];
        w[4 * q + 0] = v.x; w[4 * q + 1] = v.y;
        w[4 * q + 2] = v.z; w[4 * q + 3] = v.w;
    }

    hbuf[0][tid] = 0.f;
    __syncthreads();
    asm volatile("barrier.cluster.arrive.aligned;" ::: "memory");
    asm volatile("barrier.cluster.wait.aligned;" ::: "memory");

    const float* xp_ptr  = g_xproj + (size_t)b * Tt * Hh + grow;
    float*       hall_ptr = g_hall + (size_t)b * Tt * Hh + grow;

    // depth-2 prefetch of xproj (low threads only)
    float xp0 = 0.f, xp1 = 0.f;
    if (low) {
        xp0 = xp_ptr[0];
        xp1 = xp_ptr[Hh];
    }

    int cur = 0;
    for (int t = 0; t < Tt; t++) {
        float xp2 = 0.f;
        if (low && (t + 2) < Tt) xp2 = xp_ptr[(size_t)(t + 2) * Hh];

        const float* h = hbuf[cur] + kbase;
        float a0 = 0.f, a1 = 0.f, a2 = 0.f, a3 = 0.f;
#pragma unroll
        for (int q = 0; q < 32; q++) {
            float4 hv = *(const float4*)(h + 4 * q);
            a0 = fmaf(w[4 * q + 0], hv.x, a0);
            a1 = fmaf(w[4 * q + 1], hv.y, a1);
            a2 = fmaf(w[4 * q + 2], hv.z, a2);
            a3 = fmaf(w[4 * q + 3], hv.w, a3);
        }
        float acc = (a0 + a1) + (a2 + a3);

        if (!low) part[r] = acc;
        __syncthreads();
        if (low) {
            float v = tanhf(acc + part[r] + xp0);
            hbuf[cur ^ 1][grow] = v;                 // own smem
            unsigned laddr = smem_u32(&hbuf[cur ^ 1][grow]);
            asm volatile(
                "{\n\t.reg .b32 ra;\n\t"
                "mapa.shared::cluster.u32 ra, %0, %1;\n\t"
                "st.shared::cluster.f32 [ra], %2;\n\t}"
                :: "r"(laddr), "r"(peer), "f"(v) : "memory");
            hall_ptr[(size_t)t * Hh] = v;            // defer output projection
            xp0 = xp1; xp1 = xp2;
        }
        // release own writes (incl. DSMEM) / acquire peer's
        asm volatile("barrier.cluster.arrive.aligned;" ::: "memory");
        asm volatile("barrier.cluster.wait.aligned;" ::: "memory");
        cur ^= 1;
    }
}

// ============================================================================
// launch
// ============================================================================
extern "C" void kernel_launch(void* const* d_in, const int* in_sizes, int n_in,
                              void* d_out, int out_size) {
    const float* x      = (const float*)d_in[0];
    const float* W_in   = (const float*)d_in[1];
    const float* b_in   = (const float*)d_in[2];
    const float* W_out  = (const float*)d_in[3];
    const float* b_out  = (const float*)d_in[4];
    const float* u_raw  = (const float*)d_in[5];
    const float* sigmas = (const float*)d_in[6];
    const float* v_raw  = (const float*)d_in[7];
    float* out = (float*)d_out;

    void* xp_v = nullptr;
    void* hall_v = nullptr;
    cudaGetSymbolAddress(&xp_v, g_xproj);
    cudaGetSymbolAddress(&hall_v, g_hall);
    float* xp = (float*)xp_v;
    float* hall = (float*)hall_v;

    // 1) masked/flipped Householder vectors + betas
    prep_kernel<<<512, 256>>>(u_raw, v_raw);
    // 2) column-parallel Householder chains -> U, V
    chain_kernel<<<64, 256>>>();
    // 3) W = (U * sigma) @ V
    wgemm_kernel<<<256, 256>>>(sigmas);
    // 4) xproj[b,t,:] = W_in @ x[b,t,:] + b_in   (M=B*T, N=H, K=I)
    sgemm_nt<<<dim3(Hh / 128, (Bb * Tt) / 128), 256>>>(x, W_in, b_in, xp,
                                                       Bb * Tt, Hh, Ii);
    // 5) recurrence (writes g_hall)
    rnn_kernel<<<Bb * 2, 256>>>();
    // 6) out[b,t,:] = W_out @ h[b,t,:] + b_out   (M=B*T, N=O, K=H)
    sgemm_nt<<<dim3(Oo / 128, (Bb * Tt) / 128), 256>>>(hall, W_out, b_out, out,
                                                       Bb * Tt, Oo, Hh);
}